// round 3
// baseline (speedup 1.0000x reference)
#include <cuda_runtime.h>

#define HID 50
#define NPTS 8192
#define NPARA 5000
#define WARPS_PER_BLOCK 8
#define THREADS (WARPS_PER_BLOCK * 32)
#define NBLOCKS (NPTS / WARPS_PER_BLOCK)

// shared layout (floats)
#define OFF_WIN 0
#define OFF_BIN 150
#define OFF_WH  200
#define OFF_BH  10200
#define OFF_WO  10400
#define OFF_BO  10500
#define OFF_STATE 10504                 // byte 42016, 16B aligned
#define STATE_STRIDE 600                // 50 units * 12 floats (dup) = 2400B per warp
#define OFF_OUT8 (OFF_STATE + WARPS_PER_BLOCK * STATE_STRIDE)   // 15304
#define OFF_PART (OFF_OUT8 + WARPS_PER_BLOCK * 8)               // 15368
#define OFF_FLAG (OFF_PART + WARPS_PER_BLOCK * 6)               // 15416
#define SMEM_FLOATS (OFF_FLAG + 4)
#define SMEM_BYTES (SMEM_FLOATS * 4)    // ~61.7KB -> 3 blocks/SM

typedef unsigned long long u64;

__device__ double g_sums[6];
__device__ unsigned int g_ticket;

__device__ __forceinline__ u64 pack2(float lo, float hi) {
    u64 r; asm("mov.b64 %0, {%1, %2};" : "=l"(r) : "f"(lo), "f"(hi)); return r;
}
__device__ __forceinline__ void unpack2(u64 v, float& lo, float& hi) {
    asm("mov.b64 {%0, %1}, %2;" : "=f"(lo), "=f"(hi) : "l"(v));
}
// d.lo += a.lo*b.lo ; d.hi += a.hi*b.hi   (SASS FFMA2, PTX-only)
__device__ __forceinline__ void ffma2(u64& d, u64 a, u64 b) {
    asm("fma.rn.f32x2 %0, %1, %2, %0;" : "+l"(d) : "l"(a), "l"(b));
}

// tanh(z) and sech^2(z): r = 1/(e^{2z}+1); h = 1-2r; 1-h^2 = 4r(1-r)
__device__ __forceinline__ void tanh_s(float z, float& h, float& s) {
    float e = __expf(2.0f * z);
    float r = __fdividef(1.0f, e + 1.0f);
    h = 1.0f - 2.0f * r;
    s = 4.0f * r * (1.0f - r);
}

// tanh chain + duplicated state write for one unit
__device__ __forceinline__ void chain_store(float* p, float z, float zx, float zxx,
                                            float zy, float zyy, float zt) {
    float h, s; tanh_s(z, h, s);
    float d0  = s * zx;
    float dd0 = fmaf(-2.0f * h * d0, zx, s * zxx);
    float d1  = s * zy;
    float dd1 = fmaf(-2.0f * h * d1, zy, s * zyy);
    float d2  = s * zt;
    ((float4*)p)[0] = make_float4(h,   h,   d0,  d0);
    ((float4*)p)[1] = make_float4(dd0, dd0, d1,  d1);
    ((float4*)p)[2] = make_float4(dd1, dd1, d2,  d2);
}

__global__ void __launch_bounds__(THREADS) pinn_kernel(
    const float* __restrict__ x,
    const float* __restrict__ para,
    const float* __restrict__ W_in, const float* __restrict__ b_in,
    const float* __restrict__ W_hid, const float* __restrict__ b_hid,
    const float* __restrict__ W_out, const float* __restrict__ b_out,
    float* __restrict__ out)
{
    extern __shared__ float sm[];
    const int tid = threadIdx.x;

    // W_hid is 10000 floats, 16B-aligned both sides: vector copy
    for (int i = tid; i < 2500; i += THREADS)
        ((float4*)(sm + OFF_WH))[i] = ((const float4*)W_hid)[i];
    for (int i = tid; i < 150;  i += THREADS) sm[OFF_WIN + i] = W_in[i];
    for (int i = tid; i < 50;   i += THREADS) sm[OFF_BIN + i] = b_in[i];
    for (int i = tid; i < 200;  i += THREADS) sm[OFF_BH  + i] = b_hid[i];
    for (int i = tid; i < 100;  i += THREADS) sm[OFF_WO  + i] = W_out[i];
    if (tid < 2) sm[OFF_BO + tid] = b_out[tid];
    __syncthreads();

    const int warp = tid >> 5;
    const int lane = tid & 31;
    const int point = blockIdx.x * WARPS_PER_BLOCK + warp;
    float* st = sm + OFF_STATE + warp * STATE_STRIDE;   // dup state, 12 floats/unit
    const int lc = (lane < 25) ? lane : 24;             // lanes 25..31: clamped junk
    const int u0 = 2 * lc;

    const float x0 = x[point * 3 + 0];
    const float x1 = x[point * 3 + 1];
    const float x2 = x[point * 3 + 2];

    // ---- input layer: 2 units per lane; z'' = 0, first derivs = W_in rows
    if (lane < 25) {
        #pragma unroll
        for (int q = 0; q < 2; q++) {
            int j = u0 + q;
            float w0 = sm[OFF_WIN + j];
            float w1 = sm[OFF_WIN + 50 + j];
            float w2 = sm[OFF_WIN + 100 + j];
            float z = sm[OFF_BIN + j] + x0 * w0 + x1 * w1 + x2 * w2;
            float h, s; tanh_s(z, h, s);
            float d0  = s * w0;
            float dd0 = -2.0f * h * d0 * w0;
            float d1  = s * w1;
            float dd1 = -2.0f * h * d1 * w1;
            float d2  = s * w2;
            float* p = st + j * 12;
            ((float4*)p)[0] = make_float4(h,   h,   d0,  d0);
            ((float4*)p)[1] = make_float4(dd0, dd0, d1,  d1);
            ((float4*)p)[2] = make_float4(dd1, dd1, d2,  d2);
        }
    }
    __syncwarp();

    // ---- 4 hidden layers: unit-packed f32x2 matvec, 10 instrs per k
    for (int l = 0; l < 4; l++) {
        const float* Wl = sm + OFF_WH + l * 2500;
        const float* bl = sm + OFF_BH + l * 50;

        u64 P0 = *(const u64*)(bl + u0);    // {z_u0, z_u1}
        u64 P1 = 0ull, P2 = 0ull, P3 = 0ull, P4 = 0ull, P5 = 0ull;

        #pragma unroll
        for (int k = 0; k < HID; k++) {
            u64 ww = *(const u64*)(Wl + k * 50 + u0);           // {w_u0, w_u1}
            const ulonglong2* sp = (const ulonglong2*)(st + k * 12);
            ulonglong2 A = sp[0];   // {h,h} {dx,dx}       broadcast
            ulonglong2 B = sp[1];   // {dxx,dxx} {dy,dy}
            ulonglong2 C = sp[2];   // {dyy,dyy} {dt,dt}
            ffma2(P0, A.x, ww);
            ffma2(P1, A.y, ww);
            ffma2(P2, B.x, ww);
            ffma2(P3, B.y, ww);
            ffma2(P4, C.x, ww);
            ffma2(P5, C.y, ww);
        }
        __syncwarp();   // all reads of old state done before overwrite
        if (lane < 25) {
            float z0, z1, zx0, zx1, zxx0, zxx1, zy0, zy1, zyy0, zyy1, zt0, zt1;
            unpack2(P0, z0, z1);   unpack2(P1, zx0, zx1);  unpack2(P2, zxx0, zxx1);
            unpack2(P3, zy0, zy1); unpack2(P4, zyy0, zyy1); unpack2(P5, zt0, zt1);
            chain_store(st + u0 * 12,        z0, zx0, zxx0, zy0, zyy0, zt0);
            chain_store(st + u0 * 12 + 12,   z1, zx1, zxx1, zy1, zyy1, zt1);
        }
        __syncwarp();
    }

    // ---- output layer: channels {val,dxx,dyy,dt} x {u,v} = 8 dot products
    if (lane < 8) {
        int c4 = (lane >> 1) * 4;        // 0,4,8,12
        if (c4 == 12) c4 = 10;           // -> dup offsets 0(h),4(dxx),8(dyy),10(dt)
        int o = lane & 1;
        float acc0 = (c4 == 0) ? sm[OFF_BO + o] : 0.0f;
        float acc1 = 0.0f;
        #pragma unroll
        for (int k = 0; k < HID; k += 2) {
            acc0 = fmaf(st[k * 12 + c4],        sm[OFF_WO + k * 2 + o],       acc0);
            acc1 = fmaf(st[(k + 1) * 12 + c4],  sm[OFF_WO + (k + 1) * 2 + o], acc1);
        }
        sm[OFF_OUT8 + warp * 8 + lane] = acc0 + acc1;
    }
    __syncwarp();

    if (lane == 0) {
        const float* o8 = sm + OFF_OUT8 + warp * 8;
        float u   = o8[0], v   = o8[1];
        float uxx = o8[2], vxx = o8[3];
        float uyy = o8[4], vyy = o8[5];
        float ut  = o8[6], vt  = o8[7];
        float Q  = u * u + v * v;
        float A1 = vt - 0.5f * uxx - 0.5f * vyy - Q * u + v;
        float A2 = ut + 0.5f * vxx - 0.5f * uyy + Q * v + u;
        float B1 = uyy, B2 = vyy;
        float C1 = Q * v, C2 = Q * u;
        float* pp = sm + OFF_PART + warp * 6;
        pp[0] = A1 * A1 + A2 * A2;
        pp[1] = B1 * B1 + B2 * B2;
        pp[2] = C1 * C1 + C2 * C2;
        pp[3] = A2 * B2 - A1 * B1;
        pp[4] = A1 * C1 + A2 * C2;
        pp[5] = B1 * C1 - B2 * C2;
    }
    __syncthreads();

    if (tid < 6) {
        double s = 0.0;
        #pragma unroll
        for (int w = 0; w < WARPS_PER_BLOCK; w++)
            s += (double)sm[OFF_PART + w * 6 + tid];
        atomicAdd(&g_sums[tid], s);
    }
    __syncthreads();

    // ---- last-block-done: fused finalize
    if (tid == 0) {
        __threadfence();
        unsigned t = atomicAdd(&g_ticket, 1u);
        ((unsigned*)sm)[OFF_FLAG] = (t == (unsigned)(gridDim.x - 1)) ? 1u : 0u;
    }
    __syncthreads();

    if (((unsigned*)sm)[OFF_FLAG]) {
        double s0 = g_sums[0], s1 = g_sums[1], s2 = g_sums[2];
        double s3 = g_sums[3], s4 = g_sums[4], s5 = g_sums[5];
        for (int p = tid; p < NPARA; p += THREADS) {
            double a = (double)para[p * 3 + 0];
            double c = (double)para[p * 3 + 2];
            double r = s0 + 0.25 * a * a * s1 + c * c * s2
                     + a * s3 - 2.0 * c * s4 + a * c * s5;
            out[p] = (float)(r * (1.0 / (double)NPTS));
        }
        __syncthreads();
        if (tid == 0) {                 // reset for next graph replay
            g_ticket = 0u;
            #pragma unroll
            for (int i = 0; i < 6; i++) g_sums[i] = 0.0;
        }
    }
}

extern "C" void kernel_launch(void* const* d_in, const int* in_sizes, int n_in,
                              void* d_out, int out_size) {
    const float* x     = (const float*)d_in[0];
    const float* para  = (const float*)d_in[1];
    const float* W_in  = (const float*)d_in[2];
    const float* b_in  = (const float*)d_in[3];
    const float* W_hid = (const float*)d_in[4];
    const float* b_hid = (const float*)d_in[5];
    const float* W_out = (const float*)d_in[6];
    const float* b_out = (const float*)d_in[7];
    float* out = (float*)d_out;

    cudaFuncSetAttribute(pinn_kernel, cudaFuncAttributeMaxDynamicSharedMemorySize, SMEM_BYTES);
    pinn_kernel<<<NBLOCKS, THREADS, SMEM_BYTES>>>(
        x, para, W_in, b_in, W_hid, b_hid, W_out, b_out, out);
}

// round 4
// speedup vs baseline: 1.3477x; 1.3477x over previous
#include <cuda_runtime.h>

#define HID 50
#define NPTS 8192
#define NPARA 5000
#define WARPS_PER_BLOCK 16
#define THREADS (WARPS_PER_BLOCK * 32)
#define NBLOCKS (NPTS / WARPS_PER_BLOCK)

// shared layout (floats)
#define OFF_WIN 0
#define OFF_BIN 150
#define OFF_WH  200
#define OFF_BH  10200
#define OFF_WO  10400
#define OFF_BO  10500
#define OFF_STATE 10504                 // 16B aligned
#define STATE_STRIDE 400                // 50 units * 8 floats per warp
#define OFF_OUT8 (OFF_STATE + WARPS_PER_BLOCK * STATE_STRIDE)   // 16904
#define OFF_PART (OFF_OUT8 + WARPS_PER_BLOCK * 8)               // 17032
#define OFF_FLAG (OFF_PART + WARPS_PER_BLOCK * 6)               // 17128
#define SMEM_FLOATS (OFF_FLAG + 4)
#define SMEM_BYTES (SMEM_FLOATS * 4)    // ~68.5 KB -> 3 blocks/SM = 48 warps

__device__ double g_sums[6];
__device__ unsigned int g_ticket;

// tanh(z) and sech^2(z): r = 1/(e^{2z}+1); h = 1-2r; 1-h^2 = 4r(1-r)
__device__ __forceinline__ void tanh_s(float z, float& h, float& s) {
    float e = __expf(2.0f * z);
    float r = __fdividef(1.0f, e + 1.0f);
    h = 1.0f - 2.0f * r;
    s = 4.0f * r * (1.0f - r);
}

__global__ void __launch_bounds__(THREADS) pinn_kernel(
    const float* __restrict__ x,
    const float* __restrict__ para,
    const float* __restrict__ W_in, const float* __restrict__ b_in,
    const float* __restrict__ W_hid, const float* __restrict__ b_hid,
    const float* __restrict__ W_out, const float* __restrict__ b_out,
    float* __restrict__ out)
{
    extern __shared__ float sm[];
    const int tid = threadIdx.x;

    for (int i = tid; i < 2500; i += THREADS)
        ((float4*)(sm + OFF_WH))[i] = ((const float4*)W_hid)[i];
    for (int i = tid; i < 150;  i += THREADS) sm[OFF_WIN + i] = W_in[i];
    for (int i = tid; i < 50;   i += THREADS) sm[OFF_BIN + i] = b_in[i];
    for (int i = tid; i < 200;  i += THREADS) sm[OFF_BH  + i] = b_hid[i];
    for (int i = tid; i < 100;  i += THREADS) sm[OFF_WO  + i] = W_out[i];
    if (tid < 2) sm[OFF_BO + tid] = b_out[tid];
    __syncthreads();

    const int warp = tid >> 5;
    const int lane = tid & 31;
    const int point = blockIdx.x * WARPS_PER_BLOCK + warp;
    float* st = sm + OFF_STATE + warp * STATE_STRIDE;

    const float x0 = x[point * 3 + 0];
    const float x1 = x[point * 3 + 1];
    const float x2 = x[point * 3 + 2];

    // ---- input layer: z = x @ W_in + b_in; first derivs = W_in rows; z'' = 0
    #pragma unroll
    for (int o = 0; o < 2; o++) {
        int j = lane + 32 * o;
        if (j < HID) {
            float w0 = sm[OFF_WIN + j];
            float w1 = sm[OFF_WIN + 50 + j];
            float w2 = sm[OFF_WIN + 100 + j];
            float z = sm[OFF_BIN + j] + x0 * w0 + x1 * w1 + x2 * w2;
            float h, s; tanh_s(z, h, s);
            float d0  = s * w0;
            float dd0 = -2.0f * h * d0 * w0;
            float d1  = s * w1;
            float dd1 = -2.0f * h * d1 * w1;
            float d2  = s * w2;
            float* p = st + j * 8;
            p[0] = h; p[1] = d0; p[2] = dd0; p[3] = d1; p[4] = dd1; p[5] = d2;
        }
    }
    __syncwarp();

    // ---- 4 hidden layers: 6-channel matvec + tanh chain rule (round-1 body)
    const int j1 = lane;
    const int j2 = lane + 32;
    const bool has2 = (j2 < HID);

    for (int l = 0; l < 4; l++) {
        const float* Wl = sm + OFF_WH + l * 2500;
        const float* bl = sm + OFF_BH + l * 50;

        float a00 = bl[j1],              a01 = has2 ? bl[j2] : 0.0f;
        float a10 = 0.f, a11 = 0.f;
        float a20 = 0.f, a21 = 0.f;
        float a30 = 0.f, a31 = 0.f;
        float a40 = 0.f, a41 = 0.f;
        float a50 = 0.f, a51 = 0.f;

        #pragma unroll
        for (int k = 0; k < HID; k++) {
            float4 h03 = *(const float4*)(st + k * 8);       // ch0..3 (broadcast, 1 wf)
            float2 h45 = *(const float2*)(st + k * 8 + 4);   // ch4..5 (broadcast, 1 wf)
            float w1 = Wl[k * 50 + j1];                      // 1 wf
            float w2 = has2 ? Wl[k * 50 + j2] : 0.0f;        // 1 wf
            a00 = fmaf(h03.x, w1, a00); a01 = fmaf(h03.x, w2, a01);
            a10 = fmaf(h03.y, w1, a10); a11 = fmaf(h03.y, w2, a11);
            a20 = fmaf(h03.z, w1, a20); a21 = fmaf(h03.z, w2, a21);
            a30 = fmaf(h03.w, w1, a30); a31 = fmaf(h03.w, w2, a31);
            a40 = fmaf(h45.x, w1, a40); a41 = fmaf(h45.x, w2, a41);
            a50 = fmaf(h45.y, w1, a50); a51 = fmaf(h45.y, w2, a51);
        }
        __syncwarp();   // all reads of old state complete before overwrite
        {
            float h, s; tanh_s(a00, h, s);
            float d0  = s * a10;
            float dd0 = fmaf(-2.0f * h * d0, a10, s * a20);
            float d1  = s * a30;
            float dd1 = fmaf(-2.0f * h * d1, a30, s * a40);
            float d2  = s * a50;
            float* p = st + j1 * 8;
            p[0] = h; p[1] = d0; p[2] = dd0; p[3] = d1; p[4] = dd1; p[5] = d2;
        }
        if (has2) {
            float h, s; tanh_s(a01, h, s);
            float d0  = s * a11;
            float dd0 = fmaf(-2.0f * h * d0, a11, s * a21);
            float d1  = s * a31;
            float dd1 = fmaf(-2.0f * h * d1, a31, s * a41);
            float d2  = s * a51;
            float* p = st + j2 * 8;
            p[0] = h; p[1] = d0; p[2] = dd0; p[3] = d1; p[4] = dd1; p[5] = d2;
        }
        __syncwarp();
    }

    // ---- output layer: channels {0,2,4,5} x outputs {u,v} = 8 dot products
    if (lane < 8) {
        int ch = (lane >> 1) * 2;        // 0,2,4,6
        if (ch == 6) ch = 5;             // -> 0,2,4,5
        int o = lane & 1;
        float acc0 = (ch == 0) ? sm[OFF_BO + o] : 0.0f;
        float acc1 = 0.0f;
        #pragma unroll
        for (int k = 0; k < HID; k += 2) {
            acc0 = fmaf(st[k * 8 + ch],       sm[OFF_WO + k * 2 + o],       acc0);
            acc1 = fmaf(st[(k + 1) * 8 + ch], sm[OFF_WO + (k + 1) * 2 + o], acc1);
        }
        sm[OFF_OUT8 + warp * 8 + lane] = acc0 + acc1;
    }
    __syncwarp();

    if (lane == 0) {
        const float* o8 = sm + OFF_OUT8 + warp * 8;
        float u   = o8[0], v   = o8[1];
        float uxx = o8[2], vxx = o8[3];
        float uyy = o8[4], vyy = o8[5];
        float ut  = o8[6], vt  = o8[7];
        float Q  = u * u + v * v;
        float A1 = vt - 0.5f * uxx - 0.5f * vyy - Q * u + v;
        float A2 = ut + 0.5f * vxx - 0.5f * uyy + Q * v + u;
        float B1 = uyy, B2 = vyy;
        float C1 = Q * v, C2 = Q * u;
        float* pp = sm + OFF_PART + warp * 6;
        pp[0] = A1 * A1 + A2 * A2;
        pp[1] = B1 * B1 + B2 * B2;
        pp[2] = C1 * C1 + C2 * C2;
        pp[3] = A2 * B2 - A1 * B1;
        pp[4] = A1 * C1 + A2 * C2;
        pp[5] = B1 * C1 - B2 * C2;
    }
    __syncthreads();

    if (tid < 6) {
        double s = 0.0;
        #pragma unroll
        for (int w = 0; w < WARPS_PER_BLOCK; w++)
            s += (double)sm[OFF_PART + w * 6 + tid];
        atomicAdd(&g_sums[tid], s);
    }
    __syncthreads();

    // ---- last-block-done: fused finalize
    if (tid == 0) {
        __threadfence();
        unsigned t = atomicAdd(&g_ticket, 1u);
        ((unsigned*)sm)[OFF_FLAG] = (t == (unsigned)(gridDim.x - 1)) ? 1u : 0u;
    }
    __syncthreads();

    if (((unsigned*)sm)[OFF_FLAG]) {
        double s0 = g_sums[0], s1 = g_sums[1], s2 = g_sums[2];
        double s3 = g_sums[3], s4 = g_sums[4], s5 = g_sums[5];
        for (int p = tid; p < NPARA; p += THREADS) {
            double a = (double)para[p * 3 + 0];
            double c = (double)para[p * 3 + 2];
            double r = s0 + 0.25 * a * a * s1 + c * c * s2
                     + a * s3 - 2.0 * c * s4 + a * c * s5;
            out[p] = (float)(r * (1.0 / (double)NPTS));
        }
        __syncthreads();
        if (tid == 0) {                 // reset for next graph replay
            g_ticket = 0u;
            #pragma unroll
            for (int i = 0; i < 6; i++) g_sums[i] = 0.0;
        }
    }
}

extern "C" void kernel_launch(void* const* d_in, const int* in_sizes, int n_in,
                              void* d_out, int out_size) {
    const float* x     = (const float*)d_in[0];
    const float* para  = (const float*)d_in[1];
    const float* W_in  = (const float*)d_in[2];
    const float* b_in  = (const float*)d_in[3];
    const float* W_hid = (const float*)d_in[4];
    const float* b_hid = (const float*)d_in[5];
    const float* W_out = (const float*)d_in[6];
    const float* b_out = (const float*)d_in[7];
    float* out = (float*)d_out;

    cudaFuncSetAttribute(pinn_kernel, cudaFuncAttributeMaxDynamicSharedMemorySize, SMEM_BYTES);
    pinn_kernel<<<NBLOCKS, THREADS, SMEM_BYTES>>>(
        x, para, W_in, b_in, W_hid, b_hid, W_out, b_out, out);
}

// round 5
// speedup vs baseline: 1.8885x; 1.4013x over previous
#include <cuda_runtime.h>

#define HID 50
#define NPTS 8192
#define NPARA 5000
#define WARPS_PER_BLOCK 8
#define THREADS (WARPS_PER_BLOCK * 32)
#define NBLOCKS (NPTS / WARPS_PER_BLOCK)

// shared layout (floats)
#define OFF_WIN 0
#define OFF_BIN 150
#define OFF_WH  200
#define OFF_BH  10200
#define OFF_WO  10400
#define OFF_BO  10500
#define OFF_STATE 10504                 // 16B aligned
#define STATE_STRIDE 400                // 50 units * 8 floats per warp
#define OFF_OUT8 (OFF_STATE + WARPS_PER_BLOCK * STATE_STRIDE)
#define OFF_PART (OFF_OUT8 + WARPS_PER_BLOCK * 8)
#define SMEM_FLOATS (OFF_PART + WARPS_PER_BLOCK * 6)
#define SMEM_BYTES (SMEM_FLOATS * 4)    // ~55.3 KB -> 4 blocks/SM

__device__ double g_sums[6];            // zero-initialized at load; reset by finalize

// tanh(z) and sech^2(z): r = 1/(e^{2z}+1); h = 1-2r; 1-h^2 = 4r(1-r)
__device__ __forceinline__ void tanh_s(float z, float& h, float& s) {
    float e = __expf(2.0f * z);
    float r = __fdividef(1.0f, e + 1.0f);
    h = 1.0f - 2.0f * r;
    s = 4.0f * r * (1.0f - r);
}

__global__ void __launch_bounds__(THREADS) pinn_kernel(
    const float* __restrict__ x,
    const float* __restrict__ W_in, const float* __restrict__ b_in,
    const float* __restrict__ W_hid, const float* __restrict__ b_hid,
    const float* __restrict__ W_out, const float* __restrict__ b_out)
{
    extern __shared__ float sm[];
    const int tid = threadIdx.x;

    for (int i = tid; i < 2500; i += THREADS)
        ((float4*)(sm + OFF_WH))[i] = ((const float4*)W_hid)[i];
    for (int i = tid; i < 150;  i += THREADS) sm[OFF_WIN + i] = W_in[i];
    for (int i = tid; i < 50;   i += THREADS) sm[OFF_BIN + i] = b_in[i];
    for (int i = tid; i < 200;  i += THREADS) sm[OFF_BH  + i] = b_hid[i];
    for (int i = tid; i < 100;  i += THREADS) sm[OFF_WO  + i] = W_out[i];
    if (tid < 2) sm[OFF_BO + tid] = b_out[tid];
    __syncthreads();

    const int warp = tid >> 5;
    const int lane = tid & 31;
    const int point = blockIdx.x * WARPS_PER_BLOCK + warp;
    float* st = sm + OFF_STATE + warp * STATE_STRIDE;

    const float x0 = x[point * 3 + 0];
    const float x1 = x[point * 3 + 1];
    const float x2 = x[point * 3 + 2];

    // ---- input layer: z = x @ W_in + b_in; first derivs = W_in rows; z'' = 0
    #pragma unroll
    for (int o = 0; o < 2; o++) {
        int j = lane + 32 * o;
        if (j < HID) {
            float w0 = sm[OFF_WIN + j];
            float w1 = sm[OFF_WIN + 50 + j];
            float w2 = sm[OFF_WIN + 100 + j];
            float z = sm[OFF_BIN + j] + x0 * w0 + x1 * w1 + x2 * w2;
            float h, s; tanh_s(z, h, s);
            float d0  = s * w0;
            float dd0 = -2.0f * h * d0 * w0;
            float d1  = s * w1;
            float dd1 = -2.0f * h * d1 * w1;
            float d2  = s * w2;
            float* p = st + j * 8;
            p[0] = h; p[1] = d0; p[2] = dd0; p[3] = d1; p[4] = dd1; p[5] = d2;
        }
    }
    __syncwarp();

    // ---- 4 hidden layers: 6-channel matvec + tanh chain rule
    const int j1 = lane;
    const int j2 = lane + 32;
    const bool has2 = (j2 < HID);

    for (int l = 0; l < 4; l++) {
        const float* Wl = sm + OFF_WH + l * 2500;
        const float* bl = sm + OFF_BH + l * 50;

        float a00 = bl[j1],              a01 = has2 ? bl[j2] : 0.0f;
        float a10 = 0.f, a11 = 0.f;
        float a20 = 0.f, a21 = 0.f;
        float a30 = 0.f, a31 = 0.f;
        float a40 = 0.f, a41 = 0.f;
        float a50 = 0.f, a51 = 0.f;

        #pragma unroll
        for (int k = 0; k < HID; k++) {
            float4 h03 = *(const float4*)(st + k * 8);       // ch0..3 (broadcast)
            float2 h45 = *(const float2*)(st + k * 8 + 4);   // ch4..5 (broadcast)
            float w1 = Wl[k * 50 + j1];
            float w2 = has2 ? Wl[k * 50 + j2] : 0.0f;
            a00 = fmaf(h03.x, w1, a00); a01 = fmaf(h03.x, w2, a01);
            a10 = fmaf(h03.y, w1, a10); a11 = fmaf(h03.y, w2, a11);
            a20 = fmaf(h03.z, w1, a20); a21 = fmaf(h03.z, w2, a21);
            a30 = fmaf(h03.w, w1, a30); a31 = fmaf(h03.w, w2, a31);
            a40 = fmaf(h45.x, w1, a40); a41 = fmaf(h45.x, w2, a41);
            a50 = fmaf(h45.y, w1, a50); a51 = fmaf(h45.y, w2, a51);
        }
        __syncwarp();   // all reads of old state complete before overwrite
        {
            float h, s; tanh_s(a00, h, s);
            float d0  = s * a10;
            float dd0 = fmaf(-2.0f * h * d0, a10, s * a20);
            float d1  = s * a30;
            float dd1 = fmaf(-2.0f * h * d1, a30, s * a40);
            float d2  = s * a50;
            float* p = st + j1 * 8;
            p[0] = h; p[1] = d0; p[2] = dd0; p[3] = d1; p[4] = dd1; p[5] = d2;
        }
        if (has2) {
            float h, s; tanh_s(a01, h, s);
            float d0  = s * a11;
            float dd0 = fmaf(-2.0f * h * d0, a11, s * a21);
            float d1  = s * a31;
            float dd1 = fmaf(-2.0f * h * d1, a31, s * a41);
            float d2  = s * a51;
            float* p = st + j2 * 8;
            p[0] = h; p[1] = d0; p[2] = dd0; p[3] = d1; p[4] = dd1; p[5] = d2;
        }
        __syncwarp();
    }

    // ---- output layer: channels {0,2,4,5} x outputs {u,v} = 8 dot products
    if (lane < 8) {
        int ch = (lane >> 1) * 2;        // 0,2,4,6
        if (ch == 6) ch = 5;             // -> 0,2,4,5
        int o = lane & 1;
        float acc0 = (ch == 0) ? sm[OFF_BO + o] : 0.0f;
        float acc1 = 0.0f;
        #pragma unroll
        for (int k = 0; k < HID; k += 2) {
            acc0 = fmaf(st[k * 8 + ch],       sm[OFF_WO + k * 2 + o],       acc0);
            acc1 = fmaf(st[(k + 1) * 8 + ch], sm[OFF_WO + (k + 1) * 2 + o], acc1);
        }
        sm[OFF_OUT8 + warp * 8 + lane] = acc0 + acc1;
    }
    __syncwarp();

    if (lane == 0) {
        const float* o8 = sm + OFF_OUT8 + warp * 8;
        float u   = o8[0], v   = o8[1];
        float uxx = o8[2], vxx = o8[3];
        float uyy = o8[4], vyy = o8[5];
        float ut  = o8[6], vt  = o8[7];
        float Q  = u * u + v * v;
        float A1 = vt - 0.5f * uxx - 0.5f * vyy - Q * u + v;
        float A2 = ut + 0.5f * vxx - 0.5f * uyy + Q * v + u;
        float B1 = uyy, B2 = vyy;
        float C1 = Q * v, C2 = Q * u;
        float* pp = sm + OFF_PART + warp * 6;
        pp[0] = A1 * A1 + A2 * A2;
        pp[1] = B1 * B1 + B2 * B2;
        pp[2] = C1 * C1 + C2 * C2;
        pp[3] = A2 * B2 - A1 * B1;
        pp[4] = A1 * C1 + A2 * C2;
        pp[5] = B1 * C1 - B2 * C2;
    }
    __syncthreads();

    if (tid < 6) {
        double s = 0.0;
        #pragma unroll
        for (int w = 0; w < WARPS_PER_BLOCK; w++)
            s += (double)sm[OFF_PART + w * 6 + tid];
        atomicAdd(&g_sums[tid], s);
    }
}

// Reads sums, writes output, then RESETS sums for the next graph replay.
// Kernel boundary ordering makes this safe; device globals start zeroed.
__global__ void finalize_kernel(const float* __restrict__ para, float* __restrict__ out) {
    int p = blockIdx.x * blockDim.x + threadIdx.x;
    if (p < NPARA) {
        double a = (double)para[p * 3 + 0];
        double c = (double)para[p * 3 + 2];
        double r = g_sums[0]
                 + 0.25 * a * a * g_sums[1]
                 + c * c * g_sums[2]
                 + a * g_sums[3]
                 - 2.0 * c * g_sums[4]
                 + a * c * g_sums[5];
        out[p] = (float)(r * (1.0 / (double)NPTS));
    }
}

__global__ void reset_kernel() {
    if (threadIdx.x < 6) g_sums[threadIdx.x] = 0.0;
}

extern "C" void kernel_launch(void* const* d_in, const int* in_sizes, int n_in,
                              void* d_out, int out_size) {
    const float* x     = (const float*)d_in[0];
    const float* para  = (const float*)d_in[1];
    const float* W_in  = (const float*)d_in[2];
    const float* b_in  = (const float*)d_in[3];
    const float* W_hid = (const float*)d_in[4];
    const float* b_hid = (const float*)d_in[5];
    const float* W_out = (const float*)d_in[6];
    const float* b_out = (const float*)d_in[7];
    float* out = (float*)d_out;

    cudaFuncSetAttribute(pinn_kernel, cudaFuncAttributeMaxDynamicSharedMemorySize, SMEM_BYTES);
    pinn_kernel<<<NBLOCKS, THREADS, SMEM_BYTES>>>(
        x, W_in, b_in, W_hid, b_hid, W_out, b_out);
    finalize_kernel<<<(NPARA + 255) / 256, 256>>>(para, out);
    reset_kernel<<<1, 32>>>();   // cheap 1-block reset AFTER finalize (replay-safe)
}